// round 3
// baseline (speedup 1.0000x reference)
#include <cuda_runtime.h>
#include <math.h>

#define NB 8
#define C 96
#define G 4
#define CG 24
#define HH 56
#define HW 3136
#define P 25088            // NB*HW
#define HD 384
#define NCHW (NB*C*HW)     // 2408448
#define EPSF 1e-12f

typedef unsigned long long ull;

__device__ __forceinline__ ull fma2(ull a, ull b, ull c){
    ull d; asm("fma.rn.f32x2 %0, %1, %2, %3;" : "=l"(d) : "l"(a), "l"(b), "l"(c));
    return d;
}
__device__ __forceinline__ ull dup2(float v){
    ull d; asm("mov.b64 %0, {%1, %1};" : "=l"(d) : "f"(v));
    return d;
}
__device__ __forceinline__ void unpack2(ull a, float& lo, float& hi){
    asm("mov.b64 {%0, %1}, %2;" : "=f"(lo), "=f"(hi) : "l"(a));
}

// ---------------- device scratch (no allocations allowed) ----------------
__device__ float g_xnn[NCHW];     // relu(LN1(x)) channel-normalized
__device__ float g_h[NCHW];       // NNMF h (unnormalized; normalized on read)
__device__ float g_t[NCHW];       // ratio buffer, later x2 = x + attn
__device__ float g_lncf[NCHW];    // LN2 output, [c][p] channels-first
__device__ float g_hid[P*HD];     // MLP hidden
__device__ float g_wf[C*CG*9];    // normalized fwd weights  [g][ci][tap][co]
__device__ float g_wb[C*CG*9];    // transposed+flipped      [g][ci'][tap'][co']
__device__ float g_sum4[G*P];     // per-group per-pixel channel sums of g_h

__device__ __forceinline__ float gelu_exact(float v){
    return 0.5f * v * (1.0f + erff(v * 0.70710678118654752f));
}

// ---------------- weight prep: |w| L1-normalized per out-channel ----------
__global__ void prep_w_kernel(const float* __restrict__ wn){
    int o = blockIdx.x;          // 0..95
    int lane = threadIdx.x;      // 0..31
    float s = 0.f;
    for (int i = lane; i < 216; i += 32) s += fabsf(wn[o*216 + i]);
    #pragma unroll
    for (int off = 16; off; off >>= 1) s += __shfl_xor_sync(0xffffffffu, s, off);
    float inv = 1.0f / (s + EPSF);
    int g = o / 24, oo = o % 24;
    for (int i = lane; i < 216; i += 32){
        int ci = i / 9, t = i % 9;
        float v = fabsf(wn[o*216 + i]) * inv;
        g_wf[g*5184 + (ci*9 + t)*24 + oo] = v;
        g_wb[g*5184 + (oo*9 + (8 - t))*24 + ci] = v;
    }
}

// ---- LN1 (channels-first) + relu + channel-normalize; init h, sums ------
__global__ void ln1_kernel(const float* __restrict__ x,
                           const float* __restrict__ lw,
                           const float* __restrict__ lb){
    int p = blockIdx.x*256 + threadIdx.x;
    if (p >= P) return;
    int n = p / HW, hw = p % HW;
    const float* xb = x + n*C*HW + hw;
    float s1 = 0.f, s2 = 0.f;
    for (int c = 0; c < C; c++){ float v = xb[c*HW]; s1 += v; s2 += v*v; }
    float u = s1 * (1.0f/96.0f);
    float var = s2 * (1.0f/96.0f) - u*u;
    float rs = rsqrtf(var + 1e-6f);
    float sr = 0.f;
    for (int c = 0; c < C; c++){
        float v = (xb[c*HW] - u) * rs * lw[c] + lb[c];
        sr += fmaxf(v, 0.f);
    }
    float inv = 1.0f / (sr + EPSF);
    float* ob = g_xnn + n*C*HW + hw;
    float* hb = g_h   + n*C*HW + hw;
    for (int c = 0; c < C; c++){
        float v = (xb[c*HW] - u) * rs * lw[c] + lb[c];
        ob[c*HW] = fmaxf(v, 0.f) * inv;
        hb[c*HW] = 1.0f / 96.0f;
    }
    #pragma unroll
    for (int g = 0; g < 4; g++) g_sum4[g*P + p] = 0.25f;  // total = 1
}

// ------------ grouped 3x3 conv, tile = 8 rows x 56 cols, 2 px/thread ------
// MODE 0: transpose-conv of (normalized-on-load) h; epilogue ratio -> g_t
// MODE 1: forward conv of ratio; epilogue h *= acc, per-group sums -> g_sum4
// Each thread computes pixels (r0+ty, tx) and (r0+ty+4, tx): the 6 broadcast
// weight LDS.128 per (ci,tap) feed 24 packed FMAs (2 pixels) instead of 12.
template<int MODE>
__global__ __launch_bounds__(224, 2) void conv_kernel(){
    extern __shared__ float sm[];
    float* s_in = sm;            // 24 * 10 * 58 = 13920
    float* s_w  = sm + 13920;    // 24 * 9 * 24 = 5184
    const int tid = threadIdx.x;
    const int r0 = blockIdx.x * 8;
    const int g  = blockIdx.y;
    const int n  = blockIdx.z;
    const float* __restrict__ w  = (MODE == 0) ? g_wb : g_wf;
    const float* __restrict__ in = (MODE == 0) ? g_h  : g_t;

    for (int i = tid; i < 5184; i += 224) s_w[i] = w[g*5184 + i];

    const int cb = n*96 + g*24;
    const int pbase = n*HW;
    for (int i = tid; i < 13920; i += 224){
        int ci  = i / 580;
        int rem = i - ci*580;
        int r   = rem / 58;
        int col = rem - r*58 - 1;
        int grow = r0 - 1 + r;
        float v = 0.f;
        if ((unsigned)grow < 56u && (unsigned)col < 56u){
            int pix = grow*56 + col;
            v = in[(cb + ci)*HW + pix];
            if (MODE == 0){
                int q = pbase + pix;
                float s = g_sum4[q] + g_sum4[P+q] + g_sum4[2*P+q] + g_sum4[3*P+q];
                v = v / (s + EPSF);
            }
        }
        s_in[i] = v;
    }
    __syncthreads();

    const int tx = tid % 56;
    const int ty = tid / 56;      // 0..3
    ull acc0[12], acc1[12];
    #pragma unroll
    for (int i = 0; i < 12; i++){ acc0[i] = 0ULL; acc1[i] = 0ULL; }

    for (int ci = 0; ci < 24; ci++){
        const float* si = s_in + ci*580 + ty*58 + tx;
        #pragma unroll
        for (int t = 0; t < 9; t++){
            ull v0 = dup2(si[(t/3)*58 + (t%3)]);
            ull v1 = dup2(si[(t/3 + 4)*58 + (t%3)]);
            const ulonglong2* wp = (const ulonglong2*)(s_w + (ci*9 + t)*24);
            #pragma unroll
            for (int q = 0; q < 6; q++){
                ulonglong2 wv = wp[q];
                acc0[2*q]   = fma2(v0, wv.x, acc0[2*q]);
                acc0[2*q+1] = fma2(v0, wv.y, acc0[2*q+1]);
                acc1[2*q]   = fma2(v1, wv.x, acc1[2*q]);
                acc1[2*q+1] = fma2(v1, wv.y, acc1[2*q+1]);
            }
        }
    }

    float af0[24], af1[24];
    #pragma unroll
    for (int i = 0; i < 12; i++){
        unpack2(acc0[i], af0[2*i], af0[2*i+1]);
        unpack2(acc1[i], af1[2*i], af1[2*i+1]);
    }

    const int pix0 = (r0 + ty)*56 + tx;
    const int pix1 = pix0 + 4*56;
    if (MODE == 0){
        #pragma unroll
        for (int co = 0; co < 24; co++){
            int i0 = (cb + co)*HW + pix0;
            int i1 = (cb + co)*HW + pix1;
            g_t[i0] = g_xnn[i0] / (af0[co] + EPSF);
            g_t[i1] = g_xnn[i1] / (af1[co] + EPSF);
        }
    } else {
        float s0 = 0.f, s1 = 0.f;
        #pragma unroll
        for (int co = 0; co < 24; co++){
            int i0 = (cb + co)*HW + pix0;
            int i1 = (cb + co)*HW + pix1;
            float h0 = g_h[i0] * af0[co];
            float h1 = g_h[i1] * af1[co];
            g_h[i0] = h0; g_h[i1] = h1;
            s0 += h0; s1 += h1;
        }
        g_sum4[g*P + pbase + pix0] = s0;
        g_sum4[g*P + pbase + pix1] = s1;
    }
}

// ------- fused: x2 = x + h_norm  ->  LN2 over channels -> g_lncf [c][p] ---
__global__ void resid_ln2_kernel(const float* __restrict__ x,
                                 const float* __restrict__ lw,
                                 const float* __restrict__ lb){
    int p = blockIdx.x*256 + threadIdx.x;
    if (p >= P) return;
    int n = p / HW, hw = p % HW;
    float s = g_sum4[p] + g_sum4[P+p] + g_sum4[2*P+p] + g_sum4[3*P+p];
    float inv = 1.0f / (s + EPSF);
    const float* xb = x   + n*C*HW + hw;
    const float* hb = g_h + n*C*HW + hw;
    float* tb = g_t + n*C*HW + hw;
    float s1 = 0.f, s2 = 0.f;
    for (int c = 0; c < C; c++){
        float v = xb[c*HW] + hb[c*HW]*inv;
        tb[c*HW] = v;
        s1 += v; s2 += v*v;
    }
    float u = s1 * (1.0f/96.0f);
    float var = s2 * (1.0f/96.0f) - u*u;
    float rs = rsqrtf(var + 1e-5f);
    for (int c = 0; c < C; c++)
        g_lncf[c*P + p] = (tb[c*HW] - u) * rs * lw[c] + lb[c];
}

// ---------------- GEMM1: [P,96] x [96,384] -> gelu -> g_hid --------------
__global__ __launch_bounds__(256) void gemm1_kernel(const float* __restrict__ w1,
                                                    const float* __restrict__ b1){
    __shared__ float As[96*68];
    __shared__ float Bs[96*32];
    const int tid = threadIdx.x;
    const int p0 = blockIdx.x * 64;
    const int n0 = blockIdx.y * 32;
    for (int i = tid; i < 6144; i += 256){
        int c = i >> 6, m = i & 63;
        As[c*68 + m] = g_lncf[c*P + p0 + m];
    }
    for (int i = tid; i < 3072; i += 256){
        int c = i >> 5, j = i & 31;
        Bs[c*32 + j] = w1[c*384 + n0 + j];
    }
    __syncthreads();
    const int tm = tid >> 4, tn = tid & 15;
    ull acc[4];
    #pragma unroll
    for (int i = 0; i < 4; i++) acc[i] = 0ULL;
    #pragma unroll 4
    for (int k = 0; k < 96; k++){
        float4 a = *(const float4*)(As + k*68 + tm*4);
        ull b = *(const ull*)(Bs + k*32 + tn*2);
        acc[0] = fma2(dup2(a.x), b, acc[0]);
        acc[1] = fma2(dup2(a.y), b, acc[1]);
        acc[2] = fma2(dup2(a.z), b, acc[2]);
        acc[3] = fma2(dup2(a.w), b, acc[3]);
    }
    int m = p0 + tm*4;
    int j = n0 + tn*2;
    float bj0 = b1[j], bj1 = b1[j+1];
    #pragma unroll
    for (int ii = 0; ii < 4; ii++){
        float a0, a1; unpack2(acc[ii], a0, a1);
        g_hid[(m+ii)*384 + j]     = gelu_exact(a0 + bj0);
        g_hid[(m+ii)*384 + j + 1] = gelu_exact(a1 + bj1);
    }
}

// ---- GEMM2: [P,384] x [384,96] + b2 + residual -> out (NCHW) -----------
__global__ __launch_bounds__(256) void gemm2_kernel(const float* __restrict__ w2,
                                                    const float* __restrict__ b2,
                                                    float* __restrict__ out){
    __shared__ float As[32*68];
    __shared__ float Bs[32*96];
    const int tid = threadIdx.x;
    const int p0 = blockIdx.x * 64;       // 3136 % 64 == 0: never straddles images
    const int nimg = p0 / HW;
    const int hw0  = p0 % HW;
    const int tm = tid >> 4, tn = tid & 15;
    ull acc[4][3];
    #pragma unroll
    for (int ii = 0; ii < 4; ii++)
        #pragma unroll
        for (int jp = 0; jp < 3; jp++) acc[ii][jp] = 0ULL;
    for (int kb = 0; kb < 12; kb++){
        for (int i = tid; i < 2048; i += 256){
            int m = i >> 5, k = i & 31;
            As[k*68 + m] = g_hid[(p0 + m)*384 + kb*32 + k];
        }
        for (int i = tid; i < 3072; i += 256){
            int k = i / 96, c = i - k*96;
            Bs[k*96 + c] = w2[(kb*32 + k)*96 + c];
        }
        __syncthreads();
        #pragma unroll 4
        for (int k = 0; k < 32; k++){
            float4 a = *(const float4*)(As + k*68 + tm*4);
            const float* bp = Bs + k*96 + tn*6;
            ull b0 = *(const ull*)(bp);
            ull b1v = *(const ull*)(bp + 2);
            ull b2v = *(const ull*)(bp + 4);
            ull a0 = dup2(a.x), a1 = dup2(a.y), a2 = dup2(a.z), a3 = dup2(a.w);
            acc[0][0] = fma2(a0, b0, acc[0][0]);
            acc[0][1] = fma2(a0, b1v, acc[0][1]);
            acc[0][2] = fma2(a0, b2v, acc[0][2]);
            acc[1][0] = fma2(a1, b0, acc[1][0]);
            acc[1][1] = fma2(a1, b1v, acc[1][1]);
            acc[1][2] = fma2(a1, b2v, acc[1][2]);
            acc[2][0] = fma2(a2, b0, acc[2][0]);
            acc[2][1] = fma2(a2, b1v, acc[2][1]);
            acc[2][2] = fma2(a2, b2v, acc[2][2]);
            acc[3][0] = fma2(a3, b0, acc[3][0]);
            acc[3][1] = fma2(a3, b1v, acc[3][1]);
            acc[3][2] = fma2(a3, b2v, acc[3][2]);
        }
        __syncthreads();
    }
    const int cbase = tn*6;
    #pragma unroll
    for (int jp = 0; jp < 3; jp++){
        int c0 = cbase + 2*jp;
        float bc0 = b2[c0], bc1 = b2[c0+1];
        #pragma unroll
        for (int ii = 0; ii < 4; ii++){
            float v0, v1; unpack2(acc[ii][jp], v0, v1);
            int hw = hw0 + tm*4 + ii;
            int gi0 = (nimg*96 + c0)*HW + hw;
            int gi1 = (nimg*96 + c0 + 1)*HW + hw;
            out[gi0] = v0 + bc0 + g_t[gi0];
            out[gi1] = v1 + bc1 + g_t[gi1];
        }
    }
}

// ---------------- launch ----------------
extern "C" void kernel_launch(void* const* d_in, const int* in_sizes, int n_in,
                              void* d_out, int out_size){
    const float* x    = (const float*)d_in[0];
    const float* ln1w = (const float*)d_in[1];
    const float* ln1b = (const float*)d_in[2];
    const float* wn   = (const float*)d_in[3];
    const float* ln2w = (const float*)d_in[4];
    const float* ln2b = (const float*)d_in[5];
    const float* w1   = (const float*)d_in[6];
    const float* b1   = (const float*)d_in[7];
    const float* w2   = (const float*)d_in[8];
    const float* b2   = (const float*)d_in[9];
    float* out = (float*)d_out;

    const int CONV_SMEM = (13920 + 5184) * 4;   // 76416 B
    cudaFuncSetAttribute(conv_kernel<0>, cudaFuncAttributeMaxDynamicSharedMemorySize, CONV_SMEM);
    cudaFuncSetAttribute(conv_kernel<1>, cudaFuncAttributeMaxDynamicSharedMemorySize, CONV_SMEM);

    prep_w_kernel<<<96, 32>>>(wn);
    ln1_kernel<<<98, 256>>>(x, ln1w, ln1b);

    dim3 cgrid(7, 4, 8);
    for (int it = 0; it < 25; ++it){
        conv_kernel<0><<<cgrid, 224, CONV_SMEM>>>();   // recon -> ratio (fused)
        conv_kernel<1><<<cgrid, 224, CONV_SMEM>>>();   // h update + sums (fused)
    }

    resid_ln2_kernel<<<98, 256>>>(x, ln2w, ln2b);
    gemm1_kernel<<<dim3(392, 12), 256>>>(w1, b1);
    gemm2_kernel<<<392, 256>>>(w2, b2, out);
}

// round 4
// speedup vs baseline: 1.0783x; 1.0783x over previous
#include <cuda_runtime.h>
#include <math.h>

#define NB 8
#define C 96
#define G 4
#define CG 24
#define HH 56
#define HW 3136
#define P 25088            // NB*HW
#define HD 384
#define NCHW (NB*C*HW)     // 2408448
#define EPSF 1e-12f

typedef unsigned long long ull;

__device__ __forceinline__ ull fma2(ull a, ull b, ull c){
    ull d; asm("fma.rn.f32x2 %0, %1, %2, %3;" : "=l"(d) : "l"(a), "l"(b), "l"(c));
    return d;
}
__device__ __forceinline__ ull dup2(float v){
    ull d; asm("mov.b64 %0, {%1, %1};" : "=l"(d) : "f"(v));
    return d;
}
__device__ __forceinline__ void unpack2(ull a, float& lo, float& hi){
    asm("mov.b64 {%0, %1}, %2;" : "=f"(lo), "=f"(hi) : "l"(a));
}

// ---------------- device scratch (no allocations allowed) ----------------
__device__ float g_xnn[NCHW];     // relu(LN1(x)) channel-normalized
__device__ float g_h[NCHW];       // NNMF h (unnormalized; normalized on read)
__device__ float g_t[NCHW];       // ratio buffer, later x2 = x + attn
__device__ float g_lncf[NCHW];    // LN2 output, [c][p] channels-first
__device__ float g_hid[P*HD];     // MLP hidden
__device__ float g_wf[C*CG*9];    // normalized fwd weights  [g][ci][tap][co]
__device__ float g_wb[C*CG*9];    // transposed+flipped      [g][ci'][tap'][co']
__device__ float g_sum4[G*P];     // per-group per-pixel channel sums of g_h

__device__ __forceinline__ float gelu_exact(float v){
    return 0.5f * v * (1.0f + erff(v * 0.70710678118654752f));
}

// ---------------- weight prep: |w| L1-normalized per out-channel ----------
__global__ void prep_w_kernel(const float* __restrict__ wn){
    int o = blockIdx.x;          // 0..95
    int lane = threadIdx.x;      // 0..31
    float s = 0.f;
    for (int i = lane; i < 216; i += 32) s += fabsf(wn[o*216 + i]);
    #pragma unroll
    for (int off = 16; off; off >>= 1) s += __shfl_xor_sync(0xffffffffu, s, off);
    float inv = 1.0f / (s + EPSF);
    int g = o / 24, oo = o % 24;
    for (int i = lane; i < 216; i += 32){
        int ci = i / 9, t = i % 9;
        float v = fabsf(wn[o*216 + i]) * inv;
        g_wf[g*5184 + (ci*9 + t)*24 + oo] = v;
        g_wb[g*5184 + (oo*9 + (8 - t))*24 + ci] = v;
    }
}

// ---- LN1 (channels-first) + relu + channel-normalize; init h, sums ------
__global__ void ln1_kernel(const float* __restrict__ x,
                           const float* __restrict__ lw,
                           const float* __restrict__ lb){
    int p = blockIdx.x*256 + threadIdx.x;
    if (p >= P) return;
    int n = p / HW, hw = p % HW;
    const float* xb = x + n*C*HW + hw;
    float s1 = 0.f, s2 = 0.f;
    for (int c = 0; c < C; c++){ float v = xb[c*HW]; s1 += v; s2 += v*v; }
    float u = s1 * (1.0f/96.0f);
    float var = s2 * (1.0f/96.0f) - u*u;
    float rs = rsqrtf(var + 1e-6f);
    float sr = 0.f;
    for (int c = 0; c < C; c++){
        float v = (xb[c*HW] - u) * rs * lw[c] + lb[c];
        sr += fmaxf(v, 0.f);
    }
    float inv = 1.0f / (sr + EPSF);
    float* ob = g_xnn + n*C*HW + hw;
    float* hb = g_h   + n*C*HW + hw;
    for (int c = 0; c < C; c++){
        float v = (xb[c*HW] - u) * rs * lw[c] + lb[c];
        ob[c*HW] = fmaxf(v, 0.f) * inv;
        hb[c*HW] = 1.0f / 96.0f;
    }
    #pragma unroll
    for (int g = 0; g < 4; g++) g_sum4[g*P + p] = 0.25f;  // total = 1
}

// ------------ grouped 3x3 conv, tile = 4 rows x 56 cols, 1 px/thread ------
// MODE 0: transpose-conv of (normalized-on-load) h; epilogue ratio -> g_t
// MODE 1: forward conv of ratio; epilogue h *= acc, per-group sums -> g_sum4
// Software-pipelined: inputs of ci+1 prefetched during FMAs of ci.
// smem: s_in 25*348 (1 pad channel so prefetch never branches), s_w 5184,
//       s_inv 348 (MODE0 per-pixel 1/sum, computed once per halo pixel).
#define SIN_F   (25*348)           // 8700
#define SW_OFF  SIN_F              // 8700
#define SINV_OFF (SIN_F + 5184)    // 13884
#define SM_TOT  (SINV_OFF + 348)   // 14232 floats = 56928 B

template<int MODE>
__global__ __launch_bounds__(224, 2) void conv_kernel(){
    extern __shared__ float sm[];
    float* s_in  = sm;
    float* s_w   = sm + SW_OFF;
    float* s_inv = sm + SINV_OFF;
    const int tid = threadIdx.x;
    const int r0 = blockIdx.x * 4;
    const int g  = blockIdx.y;
    const int n  = blockIdx.z;
    const float* __restrict__ w  = (MODE == 0) ? g_wb : g_wf;
    const float* __restrict__ in = (MODE == 0) ? g_h  : g_t;

    for (int i = tid; i < 5184; i += 224) s_w[i] = w[g*5184 + i];

    const int cb = n*96 + g*24;
    const int pbase = n*HW;

    if (MODE == 0){
        // phase A: per-halo-pixel inverse sum (348 pixels)
        for (int i = tid; i < 348; i += 224){
            int r   = i / 58;
            int col = i - r*58 - 1;
            int grow = r0 - 1 + r;
            float iv = 0.f;
            if ((unsigned)grow < 56u && (unsigned)col < 56u){
                int q = pbase + grow*56 + col;
                float s = g_sum4[q] + g_sum4[P+q] + g_sum4[2*P+q] + g_sum4[3*P+q];
                iv = 1.0f / (s + EPSF);
            }
            s_inv[i] = iv;
        }
        __syncthreads();
    }

    // phase B: load 24 channels x 348 halo pixels
    for (int i = tid; i < 8352; i += 224){
        int ci  = i / 348;
        int rem = i - ci*348;
        int r   = rem / 58;
        int col = rem - r*58 - 1;
        int grow = r0 - 1 + r;
        float v = 0.f;
        if ((unsigned)grow < 56u && (unsigned)col < 56u){
            v = in[(cb + ci)*HW + grow*56 + col];
            if (MODE == 0) v *= s_inv[rem];
        }
        s_in[i] = v;
    }
    // init pad channel (ci=24) so the last prefetch reads defined data
    for (int i = tid; i < 348; i += 224) s_in[24*348 + i] = 0.f;
    __syncthreads();

    const int tx = tid % 56;
    const int ty = tid / 56;
    const float* sbase = s_in + ty*58 + tx;
    ull acc[12];
    #pragma unroll
    for (int i = 0; i < 12; i++) acc[i] = 0ULL;

    float v[9], vn[9];
    #pragma unroll
    for (int t = 0; t < 9; t++) v[t] = sbase[(t/3)*58 + (t%3)];

    for (int ci = 0; ci < 24; ci++){
        const float* nb = sbase + (ci+1)*348;
        #pragma unroll
        for (int t = 0; t < 9; t++) vn[t] = nb[(t/3)*58 + (t%3)];
        #pragma unroll
        for (int t = 0; t < 9; t++){
            ull vv = dup2(v[t]);
            const ulonglong2* wp = (const ulonglong2*)(s_w + (ci*9 + t)*24);
            #pragma unroll
            for (int q = 0; q < 6; q++){
                ulonglong2 wv = wp[q];
                acc[2*q]   = fma2(vv, wv.x, acc[2*q]);
                acc[2*q+1] = fma2(vv, wv.y, acc[2*q+1]);
            }
        }
        #pragma unroll
        for (int t = 0; t < 9; t++) v[t] = vn[t];
    }

    float accf[24];
    #pragma unroll
    for (int i = 0; i < 12; i++) unpack2(acc[i], accf[2*i], accf[2*i+1]);

    const int pix = (r0 + ty)*56 + tx;
    if (MODE == 0){
        #pragma unroll
        for (int co = 0; co < 24; co++){
            int idx = (cb + co)*HW + pix;
            g_t[idx] = g_xnn[idx] / (accf[co] + EPSF);
        }
    } else {
        float s = 0.f;
        #pragma unroll
        for (int co = 0; co < 24; co++){
            int idx = (cb + co)*HW + pix;
            float hv = g_h[idx] * accf[co];
            g_h[idx] = hv;
            s += hv;
        }
        g_sum4[g*P + pbase + pix] = s;
    }
}

// ------- fused: x2 = x + h_norm  ->  LN2 over channels -> g_lncf [c][p] ---
__global__ void resid_ln2_kernel(const float* __restrict__ x,
                                 const float* __restrict__ lw,
                                 const float* __restrict__ lb){
    int p = blockIdx.x*256 + threadIdx.x;
    if (p >= P) return;
    int n = p / HW, hw = p % HW;
    float s = g_sum4[p] + g_sum4[P+p] + g_sum4[2*P+p] + g_sum4[3*P+p];
    float inv = 1.0f / (s + EPSF);
    const float* xb = x   + n*C*HW + hw;
    const float* hb = g_h + n*C*HW + hw;
    float* tb = g_t + n*C*HW + hw;
    float s1 = 0.f, s2 = 0.f;
    for (int c = 0; c < C; c++){
        float v = xb[c*HW] + hb[c*HW]*inv;
        tb[c*HW] = v;
        s1 += v; s2 += v*v;
    }
    float u = s1 * (1.0f/96.0f);
    float var = s2 * (1.0f/96.0f) - u*u;
    float rs = rsqrtf(var + 1e-5f);
    for (int c = 0; c < C; c++)
        g_lncf[c*P + p] = (tb[c*HW] - u) * rs * lw[c] + lb[c];
}

// ---------------- GEMM1: [P,96] x [96,384] -> gelu -> g_hid --------------
__global__ __launch_bounds__(256) void gemm1_kernel(const float* __restrict__ w1,
                                                    const float* __restrict__ b1){
    __shared__ float As[96*68];
    __shared__ float Bs[96*32];
    const int tid = threadIdx.x;
    const int p0 = blockIdx.x * 64;
    const int n0 = blockIdx.y * 32;
    for (int i = tid; i < 6144; i += 256){
        int c = i >> 6, m = i & 63;
        As[c*68 + m] = g_lncf[c*P + p0 + m];
    }
    for (int i = tid; i < 3072; i += 256){
        int c = i >> 5, j = i & 31;
        Bs[c*32 + j] = w1[c*384 + n0 + j];
    }
    __syncthreads();
    const int tm = tid >> 4, tn = tid & 15;
    ull acc[4];
    #pragma unroll
    for (int i = 0; i < 4; i++) acc[i] = 0ULL;
    #pragma unroll 4
    for (int k = 0; k < 96; k++){
        float4 a = *(const float4*)(As + k*68 + tm*4);
        ull b = *(const ull*)(Bs + k*32 + tn*2);
        acc[0] = fma2(dup2(a.x), b, acc[0]);
        acc[1] = fma2(dup2(a.y), b, acc[1]);
        acc[2] = fma2(dup2(a.z), b, acc[2]);
        acc[3] = fma2(dup2(a.w), b, acc[3]);
    }
    int m = p0 + tm*4;
    int j = n0 + tn*2;
    float bj0 = b1[j], bj1 = b1[j+1];
    #pragma unroll
    for (int ii = 0; ii < 4; ii++){
        float a0, a1; unpack2(acc[ii], a0, a1);
        g_hid[(m+ii)*384 + j]     = gelu_exact(a0 + bj0);
        g_hid[(m+ii)*384 + j + 1] = gelu_exact(a1 + bj1);
    }
}

// ---- GEMM2: [P,384] x [384,96] + b2 + residual -> out (NCHW) -----------
__global__ __launch_bounds__(256) void gemm2_kernel(const float* __restrict__ w2,
                                                    const float* __restrict__ b2,
                                                    float* __restrict__ out){
    __shared__ float As[32*68];
    __shared__ float Bs[32*96];
    const int tid = threadIdx.x;
    const int p0 = blockIdx.x * 64;       // 3136 % 64 == 0: never straddles images
    const int nimg = p0 / HW;
    const int hw0  = p0 % HW;
    const int tm = tid >> 4, tn = tid & 15;
    ull acc[4][3];
    #pragma unroll
    for (int ii = 0; ii < 4; ii++)
        #pragma unroll
        for (int jp = 0; jp < 3; jp++) acc[ii][jp] = 0ULL;
    for (int kb = 0; kb < 12; kb++){
        for (int i = tid; i < 2048; i += 256){
            int m = i >> 5, k = i & 31;
            As[k*68 + m] = g_hid[(p0 + m)*384 + kb*32 + k];
        }
        for (int i = tid; i < 3072; i += 256){
            int k = i / 96, c = i - k*96;
            Bs[k*96 + c] = w2[(kb*32 + k)*96 + c];
        }
        __syncthreads();
        #pragma unroll 4
        for (int k = 0; k < 32; k++){
            float4 a = *(const float4*)(As + k*68 + tm*4);
            const float* bp = Bs + k*96 + tn*6;
            ull b0 = *(const ull*)(bp);
            ull b1v = *(const ull*)(bp + 2);
            ull b2v = *(const ull*)(bp + 4);
            ull a0 = dup2(a.x), a1 = dup2(a.y), a2 = dup2(a.z), a3 = dup2(a.w);
            acc[0][0] = fma2(a0, b0, acc[0][0]);
            acc[0][1] = fma2(a0, b1v, acc[0][1]);
            acc[0][2] = fma2(a0, b2v, acc[0][2]);
            acc[1][0] = fma2(a1, b0, acc[1][0]);
            acc[1][1] = fma2(a1, b1v, acc[1][1]);
            acc[1][2] = fma2(a1, b2v, acc[1][2]);
            acc[2][0] = fma2(a2, b0, acc[2][0]);
            acc[2][1] = fma2(a2, b1v, acc[2][1]);
            acc[2][2] = fma2(a2, b2v, acc[2][2]);
            acc[3][0] = fma2(a3, b0, acc[3][0]);
            acc[3][1] = fma2(a3, b1v, acc[3][1]);
            acc[3][2] = fma2(a3, b2v, acc[3][2]);
        }
        __syncthreads();
    }
    const int cbase = tn*6;
    #pragma unroll
    for (int jp = 0; jp < 3; jp++){
        int c0 = cbase + 2*jp;
        float bc0 = b2[c0], bc1 = b2[c0+1];
        #pragma unroll
        for (int ii = 0; ii < 4; ii++){
            float v0, v1; unpack2(acc[ii][jp], v0, v1);
            int hw = hw0 + tm*4 + ii;
            int gi0 = (nimg*96 + c0)*HW + hw;
            int gi1 = (nimg*96 + c0 + 1)*HW + hw;
            out[gi0] = v0 + bc0 + g_t[gi0];
            out[gi1] = v1 + bc1 + g_t[gi1];
        }
    }
}

// ---------------- launch ----------------
extern "C" void kernel_launch(void* const* d_in, const int* in_sizes, int n_in,
                              void* d_out, int out_size){
    const float* x    = (const float*)d_in[0];
    const float* ln1w = (const float*)d_in[1];
    const float* ln1b = (const float*)d_in[2];
    const float* wn   = (const float*)d_in[3];
    const float* ln2w = (const float*)d_in[4];
    const float* ln2b = (const float*)d_in[5];
    const float* w1   = (const float*)d_in[6];
    const float* b1   = (const float*)d_in[7];
    const float* w2   = (const float*)d_in[8];
    const float* b2   = (const float*)d_in[9];
    float* out = (float*)d_out;

    const int CONV_SMEM = SM_TOT * 4;   // 56928 B
    cudaFuncSetAttribute(conv_kernel<0>, cudaFuncAttributeMaxDynamicSharedMemorySize, CONV_SMEM);
    cudaFuncSetAttribute(conv_kernel<1>, cudaFuncAttributeMaxDynamicSharedMemorySize, CONV_SMEM);

    prep_w_kernel<<<96, 32>>>(wn);
    ln1_kernel<<<98, 256>>>(x, ln1w, ln1b);

    dim3 cgrid(14, 4, 8);
    for (int it = 0; it < 25; ++it){
        conv_kernel<0><<<cgrid, 224, CONV_SMEM>>>();   // recon -> ratio (fused)
        conv_kernel<1><<<cgrid, 224, CONV_SMEM>>>();   // h update + sums (fused)
    }

    resid_ln2_kernel<<<98, 256>>>(x, ln2w, ln2b);
    gemm1_kernel<<<dim3(392, 12), 256>>>(w1, b1);
    gemm2_kernel<<<392, 256>>>(w2, b2, out);
}

// round 5
// speedup vs baseline: 1.3065x; 1.2116x over previous
#include <cuda_runtime.h>
#include <math.h>

#define NB 8
#define C 96
#define G 4
#define CG 24
#define HH 56
#define HW 3136
#define P 25088            // NB*HW
#define HD 384
#define NCHW (NB*C*HW)     // 2408448
#define EPSF 1e-12f

typedef unsigned long long ull;

__device__ __forceinline__ ull fma2(ull a, ull b, ull c){
    ull d; asm("fma.rn.f32x2 %0, %1, %2, %3;" : "=l"(d) : "l"(a), "l"(b), "l"(c));
    return d;
}
__device__ __forceinline__ ull dup2(float v){
    ull d; asm("mov.b64 %0, {%1, %1};" : "=l"(d) : "f"(v));
    return d;
}
__device__ __forceinline__ void unpack2(ull a, float& lo, float& hi){
    asm("mov.b64 {%0, %1}, %2;" : "=f"(lo), "=f"(hi) : "l"(a));
}

// ---------------- device scratch ----------------
__device__ float g_xnn[NCHW];     // relu(LN1(x)) channel-normalized
__device__ float g_h[NCHW];       // NNMF h (unnormalized; normalized on read)
__device__ float g_t[NCHW];       // ratio buffer, later x2 = x + attn
__device__ float g_lncf[NCHW];    // LN2 output, [c][p] channels-first
__device__ float g_hid[P*HD];     // MLP hidden
__device__ float g_wf2[8*2592];   // fwd weights  [g*2+hf][(ci*9+t)*12 + k]
__device__ float g_wb2[8*2592];   // bwd weights  [g*2+hf][(o*9+(8-t))*12 + k]
__device__ float g_sum8[8*P];     // per-(g,half) per-pixel partial sums of h

__device__ __forceinline__ float gelu_exact(float v){
    return 0.5f * v * (1.0f + erff(v * 0.70710678118654752f));
}

// ---------------- weight prep: |w| L1-normalized per out-channel ----------
__global__ void prep_w_kernel(const float* __restrict__ wn){
    int o = blockIdx.x;          // 0..95 global out channel
    int lane = threadIdx.x;      // 0..31
    float s = 0.f;
    for (int i = lane; i < 216; i += 32) s += fabsf(wn[o*216 + i]);
    #pragma unroll
    for (int off = 16; off; off >>= 1) s += __shfl_xor_sync(0xffffffffu, s, off);
    float inv = 1.0f / (s + EPSF);
    int g = o / 24, oo = o % 24;
    for (int i = lane; i < 216; i += 32){
        int ci = i / 9, t = i % 9;
        float v = fabsf(wn[o*216 + i]) * inv;
        // forward: out-half by oo
        g_wf2[(g*2 + oo/12)*2592 + (ci*9 + t)*12 + (oo%12)] = v;
        // backward (transpose conv): out-chan = ci (half by ci), in-chan = oo, flipped tap
        g_wb2[(g*2 + ci/12)*2592 + (oo*9 + (8 - t))*12 + (ci%12)] = v;
    }
}

// ---- LN1 (channels-first) + relu + channel-normalize; init h, sums ------
__global__ void ln1_kernel(const float* __restrict__ x,
                           const float* __restrict__ lw,
                           const float* __restrict__ lb){
    int p = blockIdx.x*256 + threadIdx.x;
    if (p >= P) return;
    int n = p / HW, hw = p % HW;
    const float* xb = x + n*C*HW + hw;
    float s1 = 0.f, s2 = 0.f;
    for (int c = 0; c < C; c++){ float v = xb[c*HW]; s1 += v; s2 += v*v; }
    float u = s1 * (1.0f/96.0f);
    float var = s2 * (1.0f/96.0f) - u*u;
    float rs = rsqrtf(var + 1e-6f);
    float sr = 0.f;
    for (int c = 0; c < C; c++){
        float v = (xb[c*HW] - u) * rs * lw[c] + lb[c];
        sr += fmaxf(v, 0.f);
    }
    float inv = 1.0f / (sr + EPSF);
    float* ob = g_xnn + n*C*HW + hw;
    float* hb = g_h   + n*C*HW + hw;
    for (int c = 0; c < C; c++){
        float v = (xb[c*HW] - u) * rs * lw[c] + lb[c];
        ob[c*HW] = fmaxf(v, 0.f) * inv;
        hb[c*HW] = 1.0f / 96.0f;
    }
    #pragma unroll
    for (int j = 0; j < 8; j++) g_sum8[j*P + p] = 0.125f;  // total = 1
}

// ---- grouped 3x3 conv: tile 8 rows x 56 cols, 2 px/thread, 12 co/CTA ----
// grid (7 row-tiles, 8 (g,half), 8 n), block 224.
// MODE 0: transpose-conv of normalized h; epilogue ratio -> g_t (12 co)
// MODE 1: forward conv of ratio; epilogue h *= acc, partial sums -> g_sum8
#define SIN_F   (24*580)            // 13920
#define SW_OFF  SIN_F
#define SINV_OFF (SIN_F + 2592)     // 16512
#define SM_TOT  (SINV_OFF + 580)    // 17092 floats = 68368 B

template<int MODE>
__global__ __launch_bounds__(224, 3) void conv_kernel(){
    extern __shared__ float sm[];
    float* s_in  = sm;
    float* s_w   = sm + SW_OFF;
    float* s_inv = sm + SINV_OFF;
    const int tid = threadIdx.x;
    const int r0 = blockIdx.x * 8;
    const int gh = blockIdx.y;        // g*2 + half
    const int n  = blockIdx.z;
    const int g  = gh >> 1;
    const float* __restrict__ w  = ((MODE == 0) ? g_wb2 : g_wf2) + gh*2592;
    const float* __restrict__ in = (MODE == 0) ? g_h  : g_t;

    for (int i = tid; i < 2592; i += 224) s_w[i] = w[i];

    const int cin_base  = n*96 + g*24;
    const int cout_base = n*96 + g*24 + (gh & 1)*12;
    const int pbase = n*HW;

    if (MODE == 0){
        for (int i = tid; i < 580; i += 224){
            int r   = i / 58;
            int col = i - r*58 - 1;
            int grow = r0 - 1 + r;
            float iv = 0.f;
            if ((unsigned)grow < 56u && (unsigned)col < 56u){
                int q = pbase + grow*56 + col;
                float s = 0.f;
                #pragma unroll
                for (int j = 0; j < 8; j++) s += g_sum8[j*P + q];
                iv = 1.0f / (s + EPSF);
            }
            s_inv[i] = iv;
        }
        __syncthreads();
    }

    for (int i = tid; i < 13920; i += 224){
        int ci  = i / 580;
        int rem = i - ci*580;
        int r   = rem / 58;
        int col = rem - r*58 - 1;
        int grow = r0 - 1 + r;
        float v = 0.f;
        if ((unsigned)grow < 56u && (unsigned)col < 56u){
            v = in[(cin_base + ci)*HW + grow*56 + col];
            if (MODE == 0) v *= s_inv[rem];
        }
        s_in[i] = v;
    }
    __syncthreads();

    const int tx = tid % 56;
    const int ty = tid / 56;          // 0..3; pixels at rows ty and ty+4
    const float* sbase = s_in + ty*58 + tx;
    ull acc[12];                      // [0..5] px0, [6..11] px1
    #pragma unroll
    for (int i = 0; i < 12; i++) acc[i] = 0ULL;

    for (int ci = 0; ci < 24; ci++){
        const float* si = sbase + ci*580;
        #pragma unroll
        for (int t = 0; t < 9; t++){
            ull d0 = dup2(si[(t/3)*58 + (t%3)]);
            ull d1 = dup2(si[(t/3 + 4)*58 + (t%3)]);
            const ulonglong2* wp = (const ulonglong2*)(s_w + (ci*9 + t)*12);
            ulonglong2 wa = wp[0];
            ulonglong2 wb = wp[1];
            ulonglong2 wc = wp[2];
            acc[0] = fma2(d0, wa.x, acc[0]);
            acc[1] = fma2(d0, wa.y, acc[1]);
            acc[2] = fma2(d0, wb.x, acc[2]);
            acc[3] = fma2(d0, wb.y, acc[3]);
            acc[4] = fma2(d0, wc.x, acc[4]);
            acc[5] = fma2(d0, wc.y, acc[5]);
            acc[6] = fma2(d1, wa.x, acc[6]);
            acc[7] = fma2(d1, wa.y, acc[7]);
            acc[8] = fma2(d1, wb.x, acc[8]);
            acc[9] = fma2(d1, wb.y, acc[9]);
            acc[10] = fma2(d1, wc.x, acc[10]);
            acc[11] = fma2(d1, wc.y, acc[11]);
        }
    }

    float af0[12], af1[12];
    #pragma unroll
    for (int i = 0; i < 6; i++){
        unpack2(acc[i],   af0[2*i], af0[2*i+1]);
        unpack2(acc[6+i], af1[2*i], af1[2*i+1]);
    }

    const int pix0 = (r0 + ty)*56 + tx;
    const int pix1 = pix0 + 224;      // +4 rows
    if (MODE == 0){
        #pragma unroll
        for (int k = 0; k < 12; k++){
            int i0 = (cout_base + k)*HW + pix0;
            int i1 = (cout_base + k)*HW + pix1;
            g_t[i0] = g_xnn[i0] / (af0[k] + EPSF);
            g_t[i1] = g_xnn[i1] / (af1[k] + EPSF);
        }
    } else {
        float s0 = 0.f, s1 = 0.f;
        #pragma unroll
        for (int k = 0; k < 12; k++){
            int i0 = (cout_base + k)*HW + pix0;
            int i1 = (cout_base + k)*HW + pix1;
            float h0 = g_h[i0] * af0[k];
            float h1 = g_h[i1] * af1[k];
            g_h[i0] = h0; g_h[i1] = h1;
            s0 += h0; s1 += h1;
        }
        g_sum8[gh*P + pbase + pix0] = s0;
        g_sum8[gh*P + pbase + pix1] = s1;
    }
}

// ------- fused: x2 = x + h_norm  ->  LN2 over channels -> g_lncf [c][p] ---
__global__ void resid_ln2_kernel(const float* __restrict__ x,
                                 const float* __restrict__ lw,
                                 const float* __restrict__ lb){
    int p = blockIdx.x*256 + threadIdx.x;
    if (p >= P) return;
    int n = p / HW, hw = p % HW;
    float s = 0.f;
    #pragma unroll
    for (int j = 0; j < 8; j++) s += g_sum8[j*P + p];
    float inv = 1.0f / (s + EPSF);
    const float* xb = x   + n*C*HW + hw;
    const float* hb = g_h + n*C*HW + hw;
    float* tb = g_t + n*C*HW + hw;
    float s1 = 0.f, s2 = 0.f;
    for (int c = 0; c < C; c++){
        float v = xb[c*HW] + hb[c*HW]*inv;
        tb[c*HW] = v;
        s1 += v; s2 += v*v;
    }
    float u = s1 * (1.0f/96.0f);
    float var = s2 * (1.0f/96.0f) - u*u;
    float rs = rsqrtf(var + 1e-5f);
    for (int c = 0; c < C; c++)
        g_lncf[c*P + p] = (tb[c*HW] - u) * rs * lw[c] + lb[c];
}

// ---------------- GEMM1: [P,96] x [96,384] -> gelu -> g_hid --------------
__global__ __launch_bounds__(256) void gemm1_kernel(const float* __restrict__ w1,
                                                    const float* __restrict__ b1){
    __shared__ float As[96*68];
    __shared__ float Bs[96*32];
    const int tid = threadIdx.x;
    const int p0 = blockIdx.x * 64;
    const int n0 = blockIdx.y * 32;
    for (int i = tid; i < 6144; i += 256){
        int c = i >> 6, m = i & 63;
        As[c*68 + m] = g_lncf[c*P + p0 + m];
    }
    for (int i = tid; i < 3072; i += 256){
        int c = i >> 5, j = i & 31;
        Bs[c*32 + j] = w1[c*384 + n0 + j];
    }
    __syncthreads();
    const int tm = tid >> 4, tn = tid & 15;
    ull acc[4];
    #pragma unroll
    for (int i = 0; i < 4; i++) acc[i] = 0ULL;
    #pragma unroll 4
    for (int k = 0; k < 96; k++){
        float4 a = *(const float4*)(As + k*68 + tm*4);
        ull b = *(const ull*)(Bs + k*32 + tn*2);
        acc[0] = fma2(dup2(a.x), b, acc[0]);
        acc[1] = fma2(dup2(a.y), b, acc[1]);
        acc[2] = fma2(dup2(a.z), b, acc[2]);
        acc[3] = fma2(dup2(a.w), b, acc[3]);
    }
    int m = p0 + tm*4;
    int j = n0 + tn*2;
    float bj0 = b1[j], bj1 = b1[j+1];
    #pragma unroll
    for (int ii = 0; ii < 4; ii++){
        float a0, a1; unpack2(acc[ii], a0, a1);
        g_hid[(m+ii)*384 + j]     = gelu_exact(a0 + bj0);
        g_hid[(m+ii)*384 + j + 1] = gelu_exact(a1 + bj1);
    }
}

// ---- GEMM2: [P,384] x [384,96] + b2 + residual -> out (NCHW) -----------
__global__ __launch_bounds__(256) void gemm2_kernel(const float* __restrict__ w2,
                                                    const float* __restrict__ b2,
                                                    float* __restrict__ out){
    __shared__ float As[32*68];
    __shared__ float Bs[32*96];
    const int tid = threadIdx.x;
    const int p0 = blockIdx.x * 64;
    const int nimg = p0 / HW;
    const int hw0  = p0 % HW;
    const int tm = tid >> 4, tn = tid & 15;
    ull acc[4][3];
    #pragma unroll
    for (int ii = 0; ii < 4; ii++)
        #pragma unroll
        for (int jp = 0; jp < 3; jp++) acc[ii][jp] = 0ULL;
    for (int kb = 0; kb < 12; kb++){
        for (int i = tid; i < 2048; i += 256){
            int m = i >> 5, k = i & 31;
            As[k*68 + m] = g_hid[(p0 + m)*384 + kb*32 + k];
        }
        for (int i = tid; i < 3072; i += 256){
            int k = i / 96, c = i - k*96;
            Bs[k*96 + c] = w2[(kb*32 + k)*96 + c];
        }
        __syncthreads();
        #pragma unroll 4
        for (int k = 0; k < 32; k++){
            float4 a = *(const float4*)(As + k*68 + tm*4);
            const float* bp = Bs + k*96 + tn*6;
            ull b0 = *(const ull*)(bp);
            ull b1v = *(const ull*)(bp + 2);
            ull b2v = *(const ull*)(bp + 4);
            ull a0 = dup2(a.x), a1 = dup2(a.y), a2 = dup2(a.z), a3 = dup2(a.w);
            acc[0][0] = fma2(a0, b0, acc[0][0]);
            acc[0][1] = fma2(a0, b1v, acc[0][1]);
            acc[0][2] = fma2(a0, b2v, acc[0][2]);
            acc[1][0] = fma2(a1, b0, acc[1][0]);
            acc[1][1] = fma2(a1, b1v, acc[1][1]);
            acc[1][2] = fma2(a1, b2v, acc[1][2]);
            acc[2][0] = fma2(a2, b0, acc[2][0]);
            acc[2][1] = fma2(a2, b1v, acc[2][1]);
            acc[2][2] = fma2(a2, b2v, acc[2][2]);
            acc[3][0] = fma2(a3, b0, acc[3][0]);
            acc[3][1] = fma2(a3, b1v, acc[3][1]);
            acc[3][2] = fma2(a3, b2v, acc[3][2]);
        }
        __syncthreads();
    }
    const int cbase = tn*6;
    #pragma unroll
    for (int jp = 0; jp < 3; jp++){
        int c0 = cbase + 2*jp;
        float bc0 = b2[c0], bc1 = b2[c0+1];
        #pragma unroll
        for (int ii = 0; ii < 4; ii++){
            float v0, v1; unpack2(acc[ii][jp], v0, v1);
            int hw = hw0 + tm*4 + ii;
            int gi0 = (nimg*96 + c0)*HW + hw;
            int gi1 = (nimg*96 + c0 + 1)*HW + hw;
            out[gi0] = v0 + bc0 + g_t[gi0];
            out[gi1] = v1 + bc1 + g_t[gi1];
        }
    }
}

// ---------------- launch ----------------
extern "C" void kernel_launch(void* const* d_in, const int* in_sizes, int n_in,
                              void* d_out, int out_size){
    const float* x    = (const float*)d_in[0];
    const float* ln1w = (const float*)d_in[1];
    const float* ln1b = (const float*)d_in[2];
    const float* wn   = (const float*)d_in[3];
    const float* ln2w = (const float*)d_in[4];
    const float* ln2b = (const float*)d_in[5];
    const float* w1   = (const float*)d_in[6];
    const float* b1   = (const float*)d_in[7];
    const float* w2   = (const float*)d_in[8];
    const float* b2   = (const float*)d_in[9];
    float* out = (float*)d_out;

    const int CONV_SMEM = SM_TOT * 4;   // 68368 B
    cudaFuncSetAttribute(conv_kernel<0>, cudaFuncAttributeMaxDynamicSharedMemorySize, CONV_SMEM);
    cudaFuncSetAttribute(conv_kernel<1>, cudaFuncAttributeMaxDynamicSharedMemorySize, CONV_SMEM);

    prep_w_kernel<<<96, 32>>>(wn);
    ln1_kernel<<<98, 256>>>(x, ln1w, ln1b);

    dim3 cgrid(7, 8, 8);   // 448 blocks
    for (int it = 0; it < 25; ++it){
        conv_kernel<0><<<cgrid, 224, CONV_SMEM>>>();   // recon -> ratio
        conv_kernel<1><<<cgrid, 224, CONV_SMEM>>>();   // h update + partial sums
    }

    resid_ln2_kernel<<<98, 256>>>(x, ln2w, ln2b);
    gemm1_kernel<<<dim3(392, 12), 256>>>(w1, b1);
    gemm2_kernel<<<392, 256>>>(w2, b2, out);
}

// round 6
// speedup vs baseline: 1.6239x; 1.2429x over previous
#include <cuda_runtime.h>
#include <math.h>

#define NB 8
#define C 96
#define G 4
#define CG 24
#define HH 56
#define HW 3136
#define P 25088            // NB*HW
#define HD 384
#define NCHW (NB*C*HW)     // 2408448
#define EPSF 1e-12f

typedef unsigned long long ull;

__device__ __forceinline__ ull fma2(ull a, ull b, ull c){
    ull d; asm("fma.rn.f32x2 %0, %1, %2, %3;" : "=l"(d) : "l"(a), "l"(b), "l"(c));
    return d;
}
__device__ __forceinline__ ull dup2(float v){
    ull d; asm("mov.b64 %0, {%1, %1};" : "=l"(d) : "f"(v));
    return d;
}
__device__ __forceinline__ void unpack2(ull a, float& lo, float& hi){
    asm("mov.b64 {%0, %1}, %2;" : "=f"(lo), "=f"(hi) : "l"(a));
}

// ---------------- device scratch ----------------
__device__ float g_xnn[NCHW];     // relu(LN1(x)) channel-normalized
__device__ float g_h[NCHW];       // NNMF h (unnormalized; normalized on read)
__device__ float g_t[NCHW];       // ratio buffer, later x2 = x + attn
__device__ float g_lncf[NCHW];    // LN2 output, [c][p] channels-first
__device__ float g_hid[P*HD];     // MLP hidden
__device__ float g_wf2[8*2592];   // fwd weights  [g*2+hf][(ci*9+t)*12 + k]
__device__ float g_wb2[8*2592];   // bwd weights  [g*2+hf][(o*9+(8-t))*12 + k]
__device__ float g_sum8[8*P];     // per-(g,half) per-pixel partial sums of h

__device__ __forceinline__ float gelu_exact(float v){
    return 0.5f * v * (1.0f + erff(v * 0.70710678118654752f));
}

// ---------------- weight prep: |w| L1-normalized per out-channel ----------
__global__ void prep_w_kernel(const float* __restrict__ wn){
    int o = blockIdx.x;          // 0..95 global out channel
    int lane = threadIdx.x;      // 0..31
    float s = 0.f;
    for (int i = lane; i < 216; i += 32) s += fabsf(wn[o*216 + i]);
    #pragma unroll
    for (int off = 16; off; off >>= 1) s += __shfl_xor_sync(0xffffffffu, s, off);
    float inv = 1.0f / (s + EPSF);
    int g = o / 24, oo = o % 24;
    for (int i = lane; i < 216; i += 32){
        int ci = i / 9, t = i % 9;
        float v = fabsf(wn[o*216 + i]) * inv;
        g_wf2[(g*2 + oo/12)*2592 + (ci*9 + t)*12 + (oo%12)] = v;
        g_wb2[(g*2 + ci/12)*2592 + (oo*9 + (8 - t))*12 + (ci%12)] = v;
    }
}

// ---- LN1 (channels-first) + relu + channel-normalize; init h, sums ------
__global__ void ln1_kernel(const float* __restrict__ x,
                           const float* __restrict__ lw,
                           const float* __restrict__ lb){
    int p = blockIdx.x*256 + threadIdx.x;
    if (p >= P) return;
    int n = p / HW, hw = p % HW;
    const float* xb = x + n*C*HW + hw;
    float s1 = 0.f, s2 = 0.f;
    for (int c = 0; c < C; c++){ float v = xb[c*HW]; s1 += v; s2 += v*v; }
    float u = s1 * (1.0f/96.0f);
    float var = s2 * (1.0f/96.0f) - u*u;
    float rs = rsqrtf(var + 1e-6f);
    float sr = 0.f;
    for (int c = 0; c < C; c++){
        float v = (xb[c*HW] - u) * rs * lw[c] + lb[c];
        sr += fmaxf(v, 0.f);
    }
    float inv = 1.0f / (sr + EPSF);
    float* ob = g_xnn + n*C*HW + hw;
    float* hb = g_h   + n*C*HW + hw;
    for (int c = 0; c < C; c++){
        float v = (xb[c*HW] - u) * rs * lw[c] + lb[c];
        ob[c*HW] = fmaxf(v, 0.f) * inv;
        hb[c*HW] = 1.0f / 96.0f;
    }
    #pragma unroll
    for (int j = 0; j < 8; j++) g_sum8[j*P + p] = 0.125f;  // total = 1
}

// ---- grouped 3x3 conv: tile 8 rows x 56 cols, 2 ADJACENT px/thread ------
// grid (7 row-tiles, 8 (g,half), 8 n), block 224 = 8 rows x 28 col-pairs.
// MODE 0: transpose-conv of normalized h; epilogue ratio -> g_t (12 co)
// MODE 1: forward conv of ratio; epilogue h *= acc, partial sums -> g_sum8
#define SIN_F   (24*580)            // 13920
#define SW_OFF  SIN_F
#define SINV_OFF (SIN_F + 2592)     // 16512
#define SM_TOT  (SINV_OFF + 580)    // 17092 floats = 68368 B

template<int MODE>
__global__ __launch_bounds__(224, 3) void conv_kernel(){
    extern __shared__ float sm[];
    float* s_in  = sm;
    float* s_w   = sm + SW_OFF;
    float* s_inv = sm + SINV_OFF;
    const int tid = threadIdx.x;
    const int r0 = blockIdx.x * 8;
    const int gh = blockIdx.y;        // g*2 + half
    const int n  = blockIdx.z;
    const int g  = gh >> 1;
    const float* __restrict__ w  = ((MODE == 0) ? g_wb2 : g_wf2) + gh*2592;
    const float* __restrict__ in = (MODE == 0) ? g_h  : g_t;

    for (int i = tid; i < 2592; i += 224) s_w[i] = w[i];

    const int cin_base  = n*96 + g*24;
    const int cout_base = n*96 + g*24 + (gh & 1)*12;
    const int pbase = n*HW;

    if (MODE == 0){
        // per-halo-pixel inverse channel-sum (interior cols only; edges unused->0)
        for (int i = tid; i < 580; i += 224){
            int r   = i / 58;
            int col = i - r*58 - 1;
            int grow = r0 - 1 + r;
            float iv = 0.f;
            if ((unsigned)grow < 56u && (unsigned)col < 56u){
                int q = pbase + grow*56 + col;
                float s = 0.f;
                #pragma unroll
                for (int j = 0; j < 8; j++) s += g_sum8[j*P + q];
                iv = 1.0f / (s + EPSF);
            }
            s_inv[i] = iv;
        }
        __syncthreads();
    }

    // ---- edge halo columns are outside the image: always zero ----
    for (int i = tid; i < 480; i += 224){
        int ci = i / 20, rem = i - ci*20;
        int row = rem >> 1, ecol = (rem & 1) * 57;
        s_in[ci*580 + row*58 + ecol] = 0.f;
    }

    // ---- interior: vectorized LDG.128, guard hoisted out of ci loop ----
    {
        const int c4  = tid % 14;          // float4 slot within row
        const int rsl = tid / 14;          // smem row slot 0..15 (active <10)
        if (rsl < 10){
            const int grow = r0 - 1 + rsl;
            const bool rok = ((unsigned)grow < 56u);
            float iv0=0,iv1=0,iv2=0,iv3=0;
            if (MODE == 0 && rok){
                const float* sv = s_inv + rsl*58 + 1 + c4*4;
                iv0 = sv[0]; iv1 = sv[1]; iv2 = sv[2]; iv3 = sv[3];
            }
            const float* gb = in + (size_t)cin_base*HW + grow*56 + c4*4;
            float* sb = s_in + rsl*58 + 1 + c4*4;
            #pragma unroll 4
            for (int ci = 0; ci < 24; ci++){
                float4 v = make_float4(0.f,0.f,0.f,0.f);
                if (rok) v = *(const float4*)(gb + ci*HW);
                if (MODE == 0){ v.x*=iv0; v.y*=iv1; v.z*=iv2; v.w*=iv3; }
                float* s = sb + ci*580;
                s[0]=v.x; s[1]=v.y; s[2]=v.z; s[3]=v.w;
            }
        }
    }
    __syncthreads();

    const int cx = tid % 28;          // col-pair index: pixels 2cx, 2cx+1
    const int ty = tid / 28;          // 0..7
    const float* sbase = s_in + ty*58 + 2*cx;
    ull acc[12];                      // [0..5] px0 co-pairs, [6..11] px1
    #pragma unroll
    for (int i = 0; i < 12; i++) acc[i] = 0ULL;

    for (int ci = 0; ci < 24; ci++){
        const float* si = sbase + ci*580;
        float v[3][4];
        #pragma unroll
        for (int dr = 0; dr < 3; dr++){
            float2 a = *(const float2*)(si + dr*58);
            float2 b = *(const float2*)(si + dr*58 + 2);
            v[dr][0]=a.x; v[dr][1]=a.y; v[dr][2]=b.x; v[dr][3]=b.y;
        }
        #pragma unroll
        for (int t = 0; t < 9; t++){
            const int dr = t/3, dc = t%3;
            ull d0 = dup2(v[dr][dc]);
            ull d1 = dup2(v[dr][dc+1]);
            const ulonglong2* wp = (const ulonglong2*)(s_w + (ci*9 + t)*12);
            ulonglong2 wa = wp[0];
            ulonglong2 wb = wp[1];
            ulonglong2 wc = wp[2];
            acc[0]  = fma2(d0, wa.x, acc[0]);
            acc[1]  = fma2(d0, wa.y, acc[1]);
            acc[2]  = fma2(d0, wb.x, acc[2]);
            acc[3]  = fma2(d0, wb.y, acc[3]);
            acc[4]  = fma2(d0, wc.x, acc[4]);
            acc[5]  = fma2(d0, wc.y, acc[5]);
            acc[6]  = fma2(d1, wa.x, acc[6]);
            acc[7]  = fma2(d1, wa.y, acc[7]);
            acc[8]  = fma2(d1, wb.x, acc[8]);
            acc[9]  = fma2(d1, wb.y, acc[9]);
            acc[10] = fma2(d1, wc.x, acc[10]);
            acc[11] = fma2(d1, wc.y, acc[11]);
        }
    }

    float af0[12], af1[12];
    #pragma unroll
    for (int i = 0; i < 6; i++){
        unpack2(acc[i],   af0[2*i], af0[2*i+1]);
        unpack2(acc[6+i], af1[2*i], af1[2*i+1]);
    }

    const int pix0 = (r0 + ty)*56 + 2*cx;     // even -> float2-aligned
    if (MODE == 0){
        #pragma unroll
        for (int k = 0; k < 12; k++){
            int idx = (cout_base + k)*HW + pix0;
            float2 xn = *(const float2*)(g_xnn + idx);
            float2 o;
            o.x = xn.x / (af0[k] + EPSF);
            o.y = xn.y / (af1[k] + EPSF);
            *(float2*)(g_t + idx) = o;
        }
    } else {
        float s0 = 0.f, s1 = 0.f;
        #pragma unroll
        for (int k = 0; k < 12; k++){
            int idx = (cout_base + k)*HW + pix0;
            float2 hv = *(const float2*)(g_h + idx);
            hv.x *= af0[k];
            hv.y *= af1[k];
            *(float2*)(g_h + idx) = hv;
            s0 += hv.x; s1 += hv.y;
        }
        float2 sv; sv.x = s0; sv.y = s1;
        *(float2*)(g_sum8 + gh*P + pbase + pix0) = sv;
    }
}

// ------- fused: x2 = x + h_norm  ->  LN2 over channels -> g_lncf [c][p] ---
__global__ void resid_ln2_kernel(const float* __restrict__ x,
                                 const float* __restrict__ lw,
                                 const float* __restrict__ lb){
    int p = blockIdx.x*256 + threadIdx.x;
    if (p >= P) return;
    int n = p / HW, hw = p % HW;
    float s = 0.f;
    #pragma unroll
    for (int j = 0; j < 8; j++) s += g_sum8[j*P + p];
    float inv = 1.0f / (s + EPSF);
    const float* xb = x   + n*C*HW + hw;
    const float* hb = g_h + n*C*HW + hw;
    float* tb = g_t + n*C*HW + hw;
    float s1 = 0.f, s2 = 0.f;
    for (int c = 0; c < C; c++){
        float v = xb[c*HW] + hb[c*HW]*inv;
        tb[c*HW] = v;
        s1 += v; s2 += v*v;
    }
    float u = s1 * (1.0f/96.0f);
    float var = s2 * (1.0f/96.0f) - u*u;
    float rs = rsqrtf(var + 1e-5f);
    for (int c = 0; c < C; c++)
        g_lncf[c*P + p] = (tb[c*HW] - u) * rs * lw[c] + lb[c];
}

// ---------------- GEMM1: [P,96] x [96,384] -> gelu -> g_hid --------------
__global__ __launch_bounds__(256) void gemm1_kernel(const float* __restrict__ w1,
                                                    const float* __restrict__ b1){
    __shared__ float As[96*68];
    __shared__ float Bs[96*32];
    const int tid = threadIdx.x;
    const int p0 = blockIdx.x * 64;
    const int n0 = blockIdx.y * 32;
    for (int i = tid; i < 6144; i += 256){
        int c = i >> 6, m = i & 63;
        As[c*68 + m] = g_lncf[c*P + p0 + m];
    }
    for (int i = tid; i < 3072; i += 256){
        int c = i >> 5, j = i & 31;
        Bs[c*32 + j] = w1[c*384 + n0 + j];
    }
    __syncthreads();
    const int tm = tid >> 4, tn = tid & 15;
    ull acc[4];
    #pragma unroll
    for (int i = 0; i < 4; i++) acc[i] = 0ULL;
    #pragma unroll 4
    for (int k = 0; k < 96; k++){
        float4 a = *(const float4*)(As + k*68 + tm*4);
        ull b = *(const ull*)(Bs + k*32 + tn*2);
        acc[0] = fma2(dup2(a.x), b, acc[0]);
        acc[1] = fma2(dup2(a.y), b, acc[1]);
        acc[2] = fma2(dup2(a.z), b, acc[2]);
        acc[3] = fma2(dup2(a.w), b, acc[3]);
    }
    int m = p0 + tm*4;
    int j = n0 + tn*2;
    float bj0 = b1[j], bj1 = b1[j+1];
    #pragma unroll
    for (int ii = 0; ii < 4; ii++){
        float a0, a1; unpack2(acc[ii], a0, a1);
        g_hid[(m+ii)*384 + j]     = gelu_exact(a0 + bj0);
        g_hid[(m+ii)*384 + j + 1] = gelu_exact(a1 + bj1);
    }
}

// ---- GEMM2: [P,384] x [384,96] + b2 + residual -> out (NCHW) -----------
__global__ __launch_bounds__(256) void gemm2_kernel(const float* __restrict__ w2,
                                                    const float* __restrict__ b2,
                                                    float* __restrict__ out){
    __shared__ float As[32*68];
    __shared__ float Bs[32*96];
    const int tid = threadIdx.x;
    const int p0 = blockIdx.x * 64;
    const int nimg = p0 / HW;
    const int hw0  = p0 % HW;
    const int tm = tid >> 4, tn = tid & 15;
    ull acc[4][3];
    #pragma unroll
    for (int ii = 0; ii < 4; ii++)
        #pragma unroll
        for (int jp = 0; jp < 3; jp++) acc[ii][jp] = 0ULL;
    for (int kb = 0; kb < 12; kb++){
        for (int i = tid; i < 2048; i += 256){
            int m = i >> 5, k = i & 31;
            As[k*68 + m] = g_hid[(p0 + m)*384 + kb*32 + k];
        }
        for (int i = tid; i < 3072; i += 256){
            int k = i / 96, c = i - k*96;
            Bs[k*96 + c] = w2[(kb*32 + k)*96 + c];
        }
        __syncthreads();
        #pragma unroll 4
        for (int k = 0; k < 32; k++){
            float4 a = *(const float4*)(As + k*68 + tm*4);
            const float* bp = Bs + k*96 + tn*6;
            ull b0 = *(const ull*)(bp);
            ull b1v = *(const ull*)(bp + 2);
            ull b2v = *(const ull*)(bp + 4);
            ull a0 = dup2(a.x), a1 = dup2(a.y), a2 = dup2(a.z), a3 = dup2(a.w);
            acc[0][0] = fma2(a0, b0, acc[0][0]);
            acc[0][1] = fma2(a0, b1v, acc[0][1]);
            acc[0][2] = fma2(a0, b2v, acc[0][2]);
            acc[1][0] = fma2(a1, b0, acc[1][0]);
            acc[1][1] = fma2(a1, b1v, acc[1][1]);
            acc[1][2] = fma2(a1, b2v, acc[1][2]);
            acc[2][0] = fma2(a2, b0, acc[2][0]);
            acc[2][1] = fma2(a2, b1v, acc[2][1]);
            acc[2][2] = fma2(a2, b2v, acc[2][2]);
            acc[3][0] = fma2(a3, b0, acc[3][0]);
            acc[3][1] = fma2(a3, b1v, acc[3][1]);
            acc[3][2] = fma2(a3, b2v, acc[3][2]);
        }
        __syncthreads();
    }
    const int cbase = tn*6;
    #pragma unroll
    for (int jp = 0; jp < 3; jp++){
        int c0 = cbase + 2*jp;
        float bc0 = b2[c0], bc1 = b2[c0+1];
        #pragma unroll
        for (int ii = 0; ii < 4; ii++){
            float v0, v1; unpack2(acc[ii][jp], v0, v1);
            int hw = hw0 + tm*4 + ii;
            int gi0 = (nimg*96 + c0)*HW + hw;
            int gi1 = (nimg*96 + c0 + 1)*HW + hw;
            out[gi0] = v0 + bc0 + g_t[gi0];
            out[gi1] = v1 + bc1 + g_t[gi1];
        }
    }
}

// ---------------- launch ----------------
extern "C" void kernel_launch(void* const* d_in, const int* in_sizes, int n_in,
                              void* d_out, int out_size){
    const float* x    = (const float*)d_in[0];
    const float* ln1w = (const float*)d_in[1];
    const float* ln1b = (const float*)d_in[2];
    const float* wn   = (const float*)d_in[3];
    const float* ln2w = (const float*)d_in[4];
    const float* ln2b = (const float*)d_in[5];
    const float* w1   = (const float*)d_in[6];
    const float* b1   = (const float*)d_in[7];
    const float* w2   = (const float*)d_in[8];
    const float* b2   = (const float*)d_in[9];
    float* out = (float*)d_out;

    const int CONV_SMEM = SM_TOT * 4;   // 68368 B
    cudaFuncSetAttribute(conv_kernel<0>, cudaFuncAttributeMaxDynamicSharedMemorySize, CONV_SMEM);
    cudaFuncSetAttribute(conv_kernel<1>, cudaFuncAttributeMaxDynamicSharedMemorySize, CONV_SMEM);

    prep_w_kernel<<<96, 32>>>(wn);
    ln1_kernel<<<98, 256>>>(x, ln1w, ln1b);

    dim3 cgrid(7, 8, 8);   // 448 blocks
    for (int it = 0; it < 25; ++it){
        conv_kernel<0><<<cgrid, 224, CONV_SMEM>>>();   // recon -> ratio
        conv_kernel<1><<<cgrid, 224, CONV_SMEM>>>();   // h update + partial sums
    }

    resid_ln2_kernel<<<98, 256>>>(x, ln2w, ln2b);
    gemm1_kernel<<<dim3(392, 12), 256>>>(w1, b1);
    gemm2_kernel<<<392, 256>>>(w2, b2, out);
}